// round 5
// baseline (speedup 1.0000x reference)
#include <cuda_runtime.h>
#include <cuda_bf16.h>

// Problem constants
#define Bx 8
#define Lx 256
#define Dx 256
#define BLD (Bx*Lx*Dx)   // 524288
#define BLL (Bx*Lx*Lx)   // 524288

typedef unsigned long long u64;

// Scratch (device globals — no allocation allowed)
__device__ float g_A[BLD], g_Bm[BLD], g_H[BLD];
__device__ float g_W[BLL];

// ---- packed f32x2 helpers (Blackwell) --------------------------------------
__device__ __forceinline__ u64 pack2(float lo, float hi) {
    u64 r; asm("mov.b64 %0,{%1,%2};" : "=l"(r) : "f"(lo), "f"(hi)); return r;
}
__device__ __forceinline__ void unpack2(u64 v, float& lo, float& hi) {
    asm("mov.b64 {%0,%1},%2;" : "=f"(lo), "=f"(hi) : "l"(v));
}
__device__ __forceinline__ u64 ffma2(u64 a, u64 b, u64 c) {
    u64 d; asm("fma.rn.f32x2 %0,%1,%2,%3;" : "=l"(d) : "l"(a), "l"(b), "l"(c)); return d;
}
__device__ __forceinline__ u64 fadd2(u64 a, u64 b) {
    u64 d; asm("add.rn.f32x2 %0,%1,%2;" : "=l"(d) : "l"(a), "l"(b)); return d;
}

// ---------------------------------------------------------------------------
// Kernel 1: projections. C[m,n] = sum_k X[m,k]*W[n,k] (NT GEMM), 3 matrices.
// BM=64, BN=64, BK=16, 256 threads, 4x4 per thread, grid (32,4,3)=384 blocks.
// X stored as duplicated pairs: one LDS.128 = two broadcast f32x2 operands.
// Double-buffered, one __syncthreads per K-tile.
// ---------------------------------------------------------------------------
__global__ __launch_bounds__(256) void proj_kernel(
    const float* __restrict__ Q,
    const float* __restrict__ Wa,
    const float* __restrict__ Wb,
    const float* __restrict__ Wd)
{
    int mat = blockIdx.z;
    const float* W = (mat == 0) ? Wa : (mat == 1) ? Wb : Wd;
    float* Out     = (mat == 0) ? g_A : (mat == 1) ? g_Bm : g_H;

    __shared__ __align__(16) float Xs[2][16][132];  // dup pairs [k][2m]
    __shared__ __align__(16) float Ws[2][16][68];   // [k][n]

    int tid = threadIdx.x;
    int m0 = blockIdx.x * 64, n0 = blockIdx.y * 64;
    int ty = tid >> 4;      // 0..15 -> 4 m-rows
    int tx = tid & 15;      // 0..15 -> 4 n-cols
    int sr = tid >> 2;      // 0..63 staging row
    int sk = (tid & 3) * 4; // 0,4,8,12

    const float* xg = Q + (m0 + sr) * Dx + sk;
    const float* wg = W + (n0 + sr) * Dx + sk;

    float4 xv = *(const float4*)xg;
    float4 wv = *(const float4*)wg;
    {
        float xc[4] = {xv.x, xv.y, xv.z, xv.w};
        float wc[4] = {wv.x, wv.y, wv.z, wv.w};
#pragma unroll
        for (int q = 0; q < 4; q++) {
            *(u64*)&Xs[0][sk + q][2 * sr] = pack2(xc[q], xc[q]);
            Ws[0][sk + q][sr] = wc[q];
        }
    }
    __syncthreads();

    u64 acc[4][2];
#pragma unroll
    for (int m = 0; m < 4; m++) { acc[m][0] = 0ull; acc[m][1] = 0ull; }

#pragma unroll 1
    for (int it = 0; it < 16; it++) {
        int buf = it & 1;
        if (it < 15) {
            xv = *(const float4*)(xg + (it + 1) * 16);
            wv = *(const float4*)(wg + (it + 1) * 16);
        }
#pragma unroll
        for (int kk = 0; kk < 16; kk++) {
            ulonglong2 xA = *(const ulonglong2*)&Xs[buf][kk][ty * 8];
            ulonglong2 xB = *(const ulonglong2*)&Xs[buf][kk][ty * 8 + 4];
            ulonglong2 wq = *(const ulonglong2*)&Ws[buf][kk][tx * 4];
            acc[0][0] = ffma2(xA.x, wq.x, acc[0][0]);
            acc[0][1] = ffma2(xA.x, wq.y, acc[0][1]);
            acc[1][0] = ffma2(xA.y, wq.x, acc[1][0]);
            acc[1][1] = ffma2(xA.y, wq.y, acc[1][1]);
            acc[2][0] = ffma2(xB.x, wq.x, acc[2][0]);
            acc[2][1] = ffma2(xB.x, wq.y, acc[2][1]);
            acc[3][0] = ffma2(xB.y, wq.x, acc[3][0]);
            acc[3][1] = ffma2(xB.y, wq.y, acc[3][1]);
        }
        if (it < 15) {
            int nb = buf ^ 1;
            float xc[4] = {xv.x, xv.y, xv.z, xv.w};
            float wc[4] = {wv.x, wv.y, wv.z, wv.w};
#pragma unroll
            for (int q = 0; q < 4; q++) {
                *(u64*)&Xs[nb][sk + q][2 * sr] = pack2(xc[q], xc[q]);
                Ws[nb][sk + q][sr] = wc[q];
            }
            __syncthreads();
        }
    }

#pragma unroll
    for (int m = 0; m < 4; m++) {
        int row = m0 + ty * 4 + m;
        ulonglong2 o; o.x = acc[m][0]; o.y = acc[m][1];
        *(ulonglong2*)(Out + row * Dx + n0 + tx * 4) = o;
    }
}

// ---------------------------------------------------------------------------
// Kernel 2: edge scores + mask + softmax -> g_W, plus tail conversion.
// Block = (b, 8 rows), 256 threads = 8 warps. Warp w: j-half jh=w>>2,
// local rows r0=2*(w&3), r1=r0+1; lane jl covers j = jh*128 + gp*64 + jl*2.
// Softmax max/sum merged across the two j-half warps via smem.
// ---------------------------------------------------------------------------
__global__ __launch_bounds__(256) void edge_kernel(
    const int* __restrict__ dep,
    const float* __restrict__ w2,
    const int* __restrict__ wl,
    float* __restrict__ dst)   // out + BLD, or nullptr
{
    int b  = blockIdx.y;
    int i0 = blockIdx.x * 8;

    __shared__ __align__(16) float Ash2[8][520];    // A rows, dup pairs
    __shared__ __align__(16) float w2d[512];        // w2 dup pairs
    __shared__ __align__(16) float Bt[2][16][258];  // [cl][j] transposed
    __shared__ float redmx[2][8], redsum[2][8];

    int tid = threadIdx.x;

    // stage 8 A rows duplicated
#pragma unroll
    for (int p = 0; p < 2; p++) {
        int e = tid * 4 + p * 1024;
        int il = e >> 8, c = e & 255;
        float4 v = *(const float4*)(g_A + (b * Lx + i0 + il) * Dx + c);
        *(u64*)&Ash2[il][2 * c]     = pack2(v.x, v.x);
        *(u64*)&Ash2[il][2 * c + 2] = pack2(v.y, v.y);
        *(u64*)&Ash2[il][2 * c + 4] = pack2(v.z, v.z);
        *(u64*)&Ash2[il][2 * c + 6] = pack2(v.w, v.w);
    }
    {
        float v = w2[tid];
        *(u64*)&w2d[2 * tid] = pack2(v, v);
    }
    if (dst && blockIdx.x == 0 && blockIdx.y == 0 && tid < Bx)
        dst[tid] = (float)wl[tid];
    float* depout = dst ? dst + Bx : nullptr;

    const float* Bbase = g_Bm + b * Lx * Dx;

    // stage Bt chunk 0 (all 256 j rows, c 0..15), transposed
    float4 pf[4];
#pragma unroll
    for (int p = 0; p < 4; p++) {
        int e = tid * 4 + p * 1024;
        int j = e >> 4, cl = e & 15;
        pf[p] = *(const float4*)(Bbase + j * Dx + cl);
    }
#pragma unroll
    for (int p = 0; p < 4; p++) {
        int e = tid * 4 + p * 1024;
        int j = e >> 4, cl = e & 15;
        Bt[0][cl + 0][j] = pf[p].x; Bt[0][cl + 1][j] = pf[p].y;
        Bt[0][cl + 2][j] = pf[p].z; Bt[0][cl + 3][j] = pf[p].w;
    }
    __syncthreads();

    int w  = tid >> 5;
    int jl = tid & 31;
    int jh = w >> 2;           // j-half 0/1
    int wr = w & 3;            // row pair
    int r0 = wr * 2, r1 = r0 + 1;
    int jbase = jh * 128;

    u64 acc0[2] = {0, 0}, acc1[2] = {0, 0};

#pragma unroll 1
    for (int ch = 0; ch < 16; ch++) {
        int buf = ch & 1;
        if (ch < 15) {
            int c0 = (ch + 1) * 16;
#pragma unroll
            for (int p = 0; p < 4; p++) {
                int e = tid * 4 + p * 1024;
                int j = e >> 4, cl = e & 15;
                pf[p] = *(const float4*)(Bbase + j * Dx + c0 + cl);
            }
        }
#pragma unroll
        for (int c2 = 0; c2 < 8; c2++) {
            int cbase = ch * 16 + c2 * 2;
            ulonglong2 A0 = *(const ulonglong2*)&Ash2[r0][cbase * 2];
            ulonglong2 A1 = *(const ulonglong2*)&Ash2[r1][cbase * 2];
            ulonglong2 UU = *(const ulonglong2*)&w2d[cbase * 2];
#pragma unroll
            for (int cc = 0; cc < 2; cc++) {
                u64 a0 = cc ? A0.y : A0.x;
                u64 a1 = cc ? A1.y : A1.x;
                u64 up = cc ? UU.y : UU.x;
                int cl = c2 * 2 + cc;
#pragma unroll
                for (int gp = 0; gp < 2; gp++) {
                    u64 bt = *(const u64*)&Bt[buf][cl][jbase + gp * 64 + jl * 2];
                    u64 s0 = fadd2(a0, bt);
                    u64 s1 = fadd2(a1, bt);
                    float x0, y0, x1, y1;
                    unpack2(s0, x0, y0);
                    unpack2(s1, x1, y1);
                    acc0[gp] = ffma2(pack2(fmaxf(x0, 0.f), fmaxf(y0, 0.f)), up, acc0[gp]);
                    acc1[gp] = ffma2(pack2(fmaxf(x1, 0.f), fmaxf(y1, 0.f)), up, acc1[gp]);
                }
            }
        }
        if (ch < 15) {
            int nb = buf ^ 1;
#pragma unroll
            for (int p = 0; p < 4; p++) {
                int e = tid * 4 + p * 1024;
                int j = e >> 4, cl = e & 15;
                Bt[nb][cl + 0][j] = pf[p].x; Bt[nb][cl + 1][j] = pf[p].y;
                Bt[nb][cl + 2][j] = pf[p].z; Bt[nb][cl + 3][j] = pf[p].w;
            }
            __syncthreads();
        }
    }

    // ---- masked softmax, merged across the two j-half warps ----
    int gi0 = b * Lx + i0 + r0;
    int gi1 = b * Lx + i0 + r1;
    float T0[4], T1[4];
    int   mk0[4], mk1[4];
    float mx0 = -1e30f, mx1 = -1e30f;
#pragma unroll
    for (int gp = 0; gp < 2; gp++) {
        int j0 = jbase + gp * 64 + jl * 2;
        int2 m0v = *(const int2*)(dep + gi0 * Lx + j0);
        int2 m1v = *(const int2*)(dep + gi1 * Lx + j0);
        float lo, hi;
        unpack2(acc0[gp], lo, hi);
        mk0[2*gp]   = (m0v.x > 0);
        mk0[2*gp+1] = (m0v.y > 0);
        T0[2*gp]    = mk0[2*gp]   ? lo : -100.0f;
        T0[2*gp+1]  = mk0[2*gp+1] ? hi : -100.0f;
        unpack2(acc1[gp], lo, hi);
        mk1[2*gp]   = (m1v.x > 0);
        mk1[2*gp+1] = (m1v.y > 0);
        T1[2*gp]    = mk1[2*gp]   ? lo : -100.0f;
        T1[2*gp+1]  = mk1[2*gp+1] ? hi : -100.0f;
        mx0 = fmaxf(mx0, fmaxf(T0[2*gp], T0[2*gp+1]));
        mx1 = fmaxf(mx1, fmaxf(T1[2*gp], T1[2*gp+1]));
        if (depout) {
            *(float2*)(depout + gi0 * Lx + j0) = make_float2((float)m0v.x, (float)m0v.y);
            *(float2*)(depout + gi1 * Lx + j0) = make_float2((float)m1v.x, (float)m1v.y);
        }
    }
#pragma unroll
    for (int off = 16; off > 0; off >>= 1) {
        mx0 = fmaxf(mx0, __shfl_xor_sync(0xffffffffu, mx0, off));
        mx1 = fmaxf(mx1, __shfl_xor_sync(0xffffffffu, mx1, off));
    }
    if (jl == 0) { redmx[jh][r0] = mx0; redmx[jh][r1] = mx1; }
    __syncthreads();
    float gmx0 = fmaxf(redmx[0][r0], redmx[1][r0]);
    float gmx1 = fmaxf(redmx[0][r1], redmx[1][r1]);

    float E0[4], E1[4], sum0 = 0.f, sum1 = 0.f;
#pragma unroll
    for (int g = 0; g < 4; g++) {
        E0[g] = expf(T0[g] - gmx0); sum0 += E0[g];
        E1[g] = expf(T1[g] - gmx1); sum1 += E1[g];
    }
#pragma unroll
    for (int off = 16; off > 0; off >>= 1) {
        sum0 += __shfl_xor_sync(0xffffffffu, sum0, off);
        sum1 += __shfl_xor_sync(0xffffffffu, sum1, off);
    }
    if (jl == 0) { redsum[jh][r0] = sum0; redsum[jh][r1] = sum1; }
    __syncthreads();
    float inv0 = 1.0f / (redsum[0][r0] + redsum[1][r0]);
    float inv1 = 1.0f / (redsum[0][r1] + redsum[1][r1]);

#pragma unroll
    for (int gp = 0; gp < 2; gp++) {
        int j0 = jbase + gp * 64 + jl * 2;
        float2 o0, o1;
        o0.x = mk0[2*gp]   ? E0[2*gp]   * inv0 : 0.f;
        o0.y = mk0[2*gp+1] ? E0[2*gp+1] * inv0 : 0.f;
        o1.x = mk1[2*gp]   ? E1[2*gp]   * inv1 : 0.f;
        o1.y = mk1[2*gp+1] ? E1[2*gp+1] * inv1 : 0.f;
        *(float2*)(g_W + gi0 * Lx + j0) = o0;
        *(float2*)(g_W + gi1 * Lx + j0) = o1;
    }
}

// ---------------------------------------------------------------------------
// Kernel 3: agg = w @ H per batch, out = relu(q + agg).  NN GEMM 256x256x256.
// BM=32, BN=64, BK=16, 256 threads, 2x4 per thread, grid (8,4,8)=256 blocks.
// W stored duplicated pairs (one LDS.128 = two broadcast f32x2 operands).
// ---------------------------------------------------------------------------
__global__ __launch_bounds__(256) void agg_kernel(
    const float* __restrict__ Q,
    float* __restrict__ out)
{
    int b  = blockIdx.z;
    int i0 = blockIdx.x * 32;
    int c0 = blockIdx.y * 64;

    __shared__ __align__(16) float Wt[2][16][68];  // [k][2*i] dup pairs
    __shared__ __align__(16) float Hs[2][16][68];  // [k][c]

    int tid = threadIdx.x;
    int ty = tid >> 4;   // 0..15 -> 2 i-rows
    int tx = tid & 15;   // 0..15 -> 4 c-cols

    int wr = (tid * 2) >> 4;        // 0..31 (W staging row)
    int wk = (tid * 2) & 15;        // even k
    int hk = tid >> 4;              // 0..15
    int hc = (tid & 15) * 4;

    const float* Wg = g_W + b * Lx * Lx + (i0 + wr) * Lx + wk;
    const float* Hg = g_H + b * Lx * Dx + hk * Dx + c0 + hc;

    float2 wv = *(const float2*)Wg;
    float4 hv = *(const float4*)Hg;
    {
        *(u64*)&Wt[0][wk][2 * wr]     = pack2(wv.x, wv.x);
        *(u64*)&Wt[0][wk + 1][2 * wr] = pack2(wv.y, wv.y);
        *(float4*)&Hs[0][hk][hc] = hv;
    }
    __syncthreads();

    u64 acc[2][2];
    acc[0][0] = acc[0][1] = acc[1][0] = acc[1][1] = 0ull;

#pragma unroll 1
    for (int it = 0; it < 16; it++) {
        int buf = it & 1;
        if (it < 15) {
            wv = *(const float2*)(Wg + (it + 1) * 16);
            hv = *(const float4*)(Hg + (it + 1) * 16 * Dx);
        }
#pragma unroll
        for (int kk = 0; kk < 16; kk++) {
            ulonglong2 wp = *(const ulonglong2*)&Wt[buf][kk][ty * 4];
            ulonglong2 hq = *(const ulonglong2*)&Hs[buf][kk][tx * 4];
            acc[0][0] = ffma2(wp.x, hq.x, acc[0][0]);
            acc[0][1] = ffma2(wp.x, hq.y, acc[0][1]);
            acc[1][0] = ffma2(wp.y, hq.x, acc[1][0]);
            acc[1][1] = ffma2(wp.y, hq.y, acc[1][1]);
        }
        if (it < 15) {
            int nb = buf ^ 1;
            *(u64*)&Wt[nb][wk][2 * wr]     = pack2(wv.x, wv.x);
            *(u64*)&Wt[nb][wk + 1][2 * wr] = pack2(wv.y, wv.y);
            *(float4*)&Hs[nb][hk][hc] = hv;
            __syncthreads();
        }
    }

#pragma unroll
    for (int m = 0; m < 2; m++) {
        int i = i0 + ty * 2 + m;
        long base = (long)(b * Lx + i) * Dx + c0 + tx * 4;
        float4 q = *(const float4*)(Q + base);
        float o0, o1, o2, o3;
        unpack2(acc[m][0], o0, o1);
        unpack2(acc[m][1], o2, o3);
        *(float4*)(out + base) = make_float4(
            fmaxf(q.x + o0, 0.f), fmaxf(q.y + o1, 0.f),
            fmaxf(q.z + o2, 0.f), fmaxf(q.w + o3, 0.f));
    }
}

// ---------------------------------------------------------------------------
extern "C" void kernel_launch(void* const* d_in, const int* in_sizes, int n_in,
                              void* d_out, int out_size)
{
    const float* Q   = (const float*)d_in[0];
    const int*   wl  = (const int*)d_in[1];
    const int*   dep = (const int*)d_in[2];
    const float* Wa  = (const float*)d_in[3];
    const float* Wb  = (const float*)d_in[4];
    const float* w2  = (const float*)d_in[5];
    const float* Wd  = (const float*)d_in[6];
    float* out = (float*)d_out;

    float* dst = (out_size >= BLD + Bx + BLL) ? out + BLD : nullptr;

    // projections: A, Bm, H (384 blocks x 256 thr)
    proj_kernel<<<dim3(32, 4, 3), 256>>>(Q, Wa, Wb, Wd);
    // edge scores + softmax -> g_W (+ tail conversions) (256 blocks x 256 thr)
    edge_kernel<<<dim3(32, Bx), 256>>>(dep, w2, wl, dst);
    // aggregation + residual relu (256 blocks x 256 thr)
    agg_kernel<<<dim3(8, 4, Bx), 256>>>(Q, out);
}